// round 3
// baseline (speedup 1.0000x reference)
#include <cuda_runtime.h>
#include <math.h>

#define Tdim 1653
#define Ddim 512
#define Bdim 2
#define Edim 8
#define DE 64
#define BE 16
#define BT (Bdim * Tdim)                  // 3306
#define TDE (Tdim * DE)                   // 105792
static const long long TT = (long long)Tdim * Tdim;   // 2732409

typedef unsigned long long u64;

// ------------------- packed f32x2 helpers ----------------------------------
__device__ __forceinline__ u64 pk2(float x, float y) {
    u64 r; asm("mov.b64 %0, {%1,%2};" : "=l"(r) : "f"(x), "f"(y)); return r;
}
__device__ __forceinline__ void fma2(u64 &d, u64 a, u64 b) {
    asm("fma.rn.f32x2 %0, %1, %2, %0;" : "+l"(d) : "l"(a), "l"(b));
}
__device__ __forceinline__ float2 up2(u64 v) {
    float2 r; asm("mov.b64 {%0,%1}, %2;" : "=f"(r.x), "=f"(r.y) : "l"(v)); return r;
}

// ------------------- scratch (static device allocations) -------------------
__device__ float g_Yq[BT * Ddim];
__device__ float g_Yk[BT * Ddim];
__device__ float g_Yv[BT * Ddim];
__device__ float g_Q [BE * TDE];          // per-head [T, 64]
__device__ float g_K [BE * TDE];          // per-head [T, 64]
__device__ float g_V [BE * TDE];          // per-head [T, 64]
__device__ float g_Wt[BE * TDE];          // per-head W^T: [64, T],  W = orth^T @ V
__device__ float g_S [(long long)BE * Tdim * Tdim];  // (Q K^T) * scale * punish
__device__ float g_O [BE * TDE];          // attention output [T, 64] per head
__device__ float g_X [BT * Ddim];         // reassembled [B,T,D]

struct Proj3 { const float* W[3]; const float* b[3]; float* Y[3]; };

// ------------------- packed NT GEMM core ------------------------------------
// C[M,N] = A[M,K] * B[N,K]^T ; BM=128, 256 threads, micro 8 x TN (TN even).
// As2 holds A values duplicated into both f32x2 lanes; Bs holds raw floats
// read back as u64 pairs (accumulator pairs run along n).
template <int BN, int TN>
__device__ __forceinline__ void gemm2_core(
    const float* __restrict__ A, const float* __restrict__ B,
    int M, int N, int K, int m0, int n0,
    u64 (&As2)[8][130], float (&Bs)[8][BN + 4], u64 (&acc)[8][TN / 2])
{
    const int tid = threadIdx.x;
    constexpr int NG = BN / TN;   // must be 16
    const int tx = tid % NG;
    const int ty = tid / NG;

#pragma unroll
    for (int i = 0; i < 8; ++i)
#pragma unroll
        for (int j = 0; j < TN / 2; ++j) acc[i][j] = 0ull;

    const int kIters = (K + 7) / 8;
    for (int kt = 0; kt < kIters; ++kt) {
        const int k0 = kt * 8;
        // A tile 128x8 -> duplicated u64
#pragma unroll
        for (int i = tid; i < 128 * 8; i += 256) {
            const int m = i >> 3, kk = i & 7;
            float v = (m0 + m < M && k0 + kk < K)
                      ? A[(long long)(m0 + m) * K + k0 + kk] : 0.f;
            As2[kk][m] = pk2(v, v);
        }
        // B tile BNx8 (float)
#pragma unroll
        for (int i = tid; i < BN * 8; i += 256) {
            const int n = i >> 3, kk = i & 7;
            Bs[kk][n] = (n0 + n < N && k0 + kk < K)
                        ? B[(long long)(n0 + n) * K + k0 + kk] : 0.f;
        }
        __syncthreads();
#pragma unroll
        for (int k = 0; k < 8; ++k) {
            u64 a2[8];
#pragma unroll
            for (int i = 0; i < 8; ++i) a2[i] = As2[k][ty * 8 + i];
            u64 b2[TN / 2];
            const u64* bp = reinterpret_cast<const u64*>(&Bs[k][tx * TN]);
#pragma unroll
            for (int j = 0; j < TN / 2; ++j) b2[j] = bp[j];
#pragma unroll
            for (int i = 0; i < 8; ++i)
#pragma unroll
                for (int j = 0; j < TN / 2; ++j)
                    fma2(acc[i][j], a2[i], b2[j]);
        }
        __syncthreads();
    }
}

// MODE 0: plain   MODE 1: +bias[n]   MODE 2: *scale*punish[m*T+n]
template <int BN, int TN, int MODE>
__global__ void __launch_bounds__(256, 2)
sgemm2_nt(const float* __restrict__ A, const float* __restrict__ B,
          float* __restrict__ C, int M, int N, int K,
          long long sA, long long sB, long long sC,
          const float* __restrict__ ep, float scale)
{
    const int bz = blockIdx.z;
    A += (long long)bz * sA;
    B += (long long)bz * sB;
    C += (long long)bz * sC;

    __shared__ __align__(16) u64   As2[8][130];
    __shared__ __align__(16) float Bs [8][BN + 4];

    const int m0 = blockIdx.y * 128;
    const int n0 = blockIdx.x * BN;
    const int tid = threadIdx.x;
    constexpr int NG = BN / TN;
    const int tx = tid % NG;
    const int ty = tid / NG;

    u64 acc[8][TN / 2];
    gemm2_core<BN, TN>(A, B, M, N, K, m0, n0, As2, Bs, acc);

#pragma unroll
    for (int i = 0; i < 8; ++i) {
        const int m = m0 + ty * 8 + i;
        if (m >= M) continue;
#pragma unroll
        for (int j = 0; j < TN / 2; ++j) {
            float2 v = up2(acc[i][j]);
            const int n = n0 + tx * TN + 2 * j;
            if (MODE == 1) {
                if (n < N)     v.x += ep[n];
                if (n + 1 < N) v.y += ep[n + 1];
            }
            if (MODE == 2) {
                if (n < N)     v.x *= scale * ep[(long long)m * Tdim + n];
                if (n + 1 < N) v.y *= scale * ep[(long long)m * Tdim + n + 1];
            }
            if (n < N)     C[(long long)m * N + n]     = v.x;
            if (n + 1 < N) C[(long long)m * N + n + 1] = v.y;
        }
    }
}

// Fused Q/K/V projections in one launch (z selects the weight set).
__global__ void __launch_bounds__(256, 2)
proj3_kernel(const float* __restrict__ X, Proj3 p)
{
    const int z = blockIdx.z;
    const float* W = p.W[z];
    const float* bias = p.b[z];
    float* Y = p.Y[z];

    __shared__ __align__(16) u64   As2[8][130];
    __shared__ __align__(16) float Bs [8][132];

    const int m0 = blockIdx.y * 128;
    const int n0 = blockIdx.x * 128;
    const int tid = threadIdx.x;
    const int tx = tid % 16;
    const int ty = tid / 16;

    u64 acc[8][4];
    gemm2_core<128, 8>(X, W, BT, Ddim, Ddim, m0, n0, As2, Bs, acc);

#pragma unroll
    for (int i = 0; i < 8; ++i) {
        const int m = m0 + ty * 8 + i;
        if (m >= BT) continue;
#pragma unroll
        for (int j = 0; j < 4; ++j) {
            float2 v = up2(acc[i][j]);
            const int n = n0 + tx * 8 + 2 * j;
            v.x += bias[n];
            v.y += bias[n + 1];
            Y[(long long)m * Ddim + n]     = v.x;
            Y[(long long)m * Ddim + n + 1] = v.y;
        }
    }
}

// ------------- W^T kernel:  Wt[d, t] = sum_s orth[s, t] * V[s, d] ----------
// per head. grid: (ceil(T/128), BE), 256 threads, micro 4(d) x 8(t) packed.
__global__ void __launch_bounds__(256, 2) wt_kernel(const float* __restrict__ orth)
{
    const int g = blockIdx.y;
    const float* V  = g_V  + (long long)g * TDE;      // [T, 64]
    const float* Og = orth + (long long)g * TT;       // [T, T]
    float* Wt = g_Wt + (long long)g * TDE;            // [64, T]

    __shared__ __align__(16) u64   Vs2[8][66];
    __shared__ __align__(16) float Os [8][132];

    const int n0 = blockIdx.x * 128;                  // t range
    const int tid = threadIdx.x;
    const int tx = tid & 15;                          // t group (x8)
    const int ty = tid >> 4;                          // d group (x4)

    u64 acc[4][4];
#pragma unroll
    for (int i = 0; i < 4; ++i)
#pragma unroll
        for (int j = 0; j < 4; ++j) acc[i][j] = 0ull;

    const int kIters = (Tdim + 7) / 8;
    for (int kt = 0; kt < kIters; ++kt) {
        const int s0 = kt * 8;
#pragma unroll
        for (int i = tid; i < 8 * 64; i += 256) {
            const int kk = i >> 6, d = i & 63;
            float v = (s0 + kk < Tdim) ? V[(long long)(s0 + kk) * DE + d] : 0.f;
            Vs2[kk][d] = pk2(v, v);
        }
#pragma unroll
        for (int i = tid; i < 8 * 128; i += 256) {
            const int kk = i >> 7, t = i & 127;
            Os[kk][t] = (s0 + kk < Tdim && n0 + t < Tdim)
                        ? Og[(long long)(s0 + kk) * Tdim + n0 + t] : 0.f;
        }
        __syncthreads();
#pragma unroll
        for (int k = 0; k < 8; ++k) {
            u64 a2[4];
#pragma unroll
            for (int i = 0; i < 4; ++i) a2[i] = Vs2[k][ty * 4 + i];
            u64 b2[4];
            const u64* bp = reinterpret_cast<const u64*>(&Os[k][tx * 8]);
#pragma unroll
            for (int j = 0; j < 4; ++j) b2[j] = bp[j];
#pragma unroll
            for (int i = 0; i < 4; ++i)
#pragma unroll
                for (int j = 0; j < 4; ++j)
                    fma2(acc[i][j], a2[i], b2[j]);
        }
        __syncthreads();
    }

#pragma unroll
    for (int i = 0; i < 4; ++i) {
        const int d = ty * 4 + i;
#pragma unroll
        for (int j = 0; j < 4; ++j) {
            float2 v = up2(acc[i][j]);
            const int t = n0 + tx * 8 + 2 * j;
            if (t < Tdim)     Wt[(long long)d * Tdim + t]     = v.x;
            if (t + 1 < Tdim) Wt[(long long)d * Tdim + t + 1] = v.y;
        }
    }
}

// ------------------- reshape / activation kernels --------------------------
__global__ void scatter_qkv_kernel()
{
    long long idx = (long long)blockIdx.x * 256 + threadIdx.x;
    const long long NTOT = (long long)BE * TDE;
    if (idx >= NTOT) return;
    const int g = (int)(idx / TDE);
    const int f = (int)(idx % TDE);
    const int b = g >> 3, e = g & 7;
    const int tt = f % Tdim;
    const int j  = f / Tdim;
    const long long src = ((long long)(b * Tdim + tt)) * Ddim + e * DE + j;

    g_Q[idx] = 1.2f / (1.f + expf(-1.6f * g_Yq[src]));
    g_K[idx] = 1.2f / (1.f + expf(-1.6f * g_Yk[src]));
    g_V[idx] = g_Yv[src];
}

__global__ void gather_x_kernel()
{
    const int idx = blockIdx.x * 256 + threadIdx.x;
    if (idx >= BT * Ddim) return;
    const int b   = idx / (Tdim * Ddim);
    const int rem = idx % (Tdim * Ddim);
    const int t = rem / Ddim, d = rem % Ddim;
    const int g = b * Edim + (d >> 6);
    g_X[idx] = g_O[((long long)g * Tdim + t) * DE + (d & 63)];
}

// ------------------- launch ------------------------------------------------
extern "C" void kernel_launch(void* const* d_in, const int* in_sizes, int n_in,
                              void* d_out, int out_size)
{
    const float* input  = (const float*)d_in[0];
    const float* Wq     = (const float*)d_in[1];
    const float* bq     = (const float*)d_in[2];
    const float* Wk     = (const float*)d_in[3];
    const float* bk     = (const float*)d_in[4];
    const float* Wv     = (const float*)d_in[5];
    const float* bv     = (const float*)d_in[6];
    const float* Wo     = (const float*)d_in[7];
    const float* bo     = (const float*)d_in[8];
    const float* punish = (const float*)d_in[9];
    const float* orth   = (const float*)d_in[10];
    float* out = (float*)d_out;

    float *Yq, *Yk, *Yv, *Q, *Kb, *S, *Wt, *O, *X;
    cudaGetSymbolAddress((void**)&Yq, g_Yq);
    cudaGetSymbolAddress((void**)&Yk, g_Yk);
    cudaGetSymbolAddress((void**)&Yv, g_Yv);
    cudaGetSymbolAddress((void**)&Q,  g_Q);
    cudaGetSymbolAddress((void**)&Kb, g_K);
    cudaGetSymbolAddress((void**)&S,  g_S);
    cudaGetSymbolAddress((void**)&Wt, g_Wt);
    cudaGetSymbolAddress((void**)&O,  g_O);
    cudaGetSymbolAddress((void**)&X,  g_X);

    const float inv_sqrt_T = 1.0f / sqrtf((float)Tdim);
    const dim3 blk(256);

    // 1) fused projections: Y = x @ W^T + b   [3306,512] x [512,512]^T  (z=3)
    {
        Proj3 p;
        p.W[0] = Wq; p.W[1] = Wk; p.W[2] = Wv;
        p.b[0] = bq; p.b[1] = bk; p.b[2] = bv;
        p.Y[0] = Yq; p.Y[1] = Yk; p.Y[2] = Yv;
        dim3 grid(512 / 128, (BT + 127) / 128, 3);
        proj3_kernel<<<grid, blk>>>(input, p);
    }

    // 2) reshape + sigmoid
    scatter_qkv_kernel<<<(BE * TDE + 255) / 256, blk>>>();

    // 3) W^T = (orth^T @ V)^T  per head
    {
        dim3 grid((Tdim + 127) / 128, BE, 1);
        wt_kernel<<<grid, blk>>>(orth);
    }

    // 4) S = (Q K^T) * (1/sqrt(T)) * punish    batched [1653,64]x[1653,64]^T
    {
        dim3 grid((Tdim + 127) / 128, (Tdim + 127) / 128, BE);
        sgemm2_nt<128, 8, 2><<<grid, blk>>>(Q, Kb, S, Tdim, Tdim, DE,
                                            (long long)TDE, (long long)TDE, TT,
                                            punish, inv_sqrt_T);
    }

    // 5) O = S @ W   == NT gemm against Wt[64, T]   batched [1653,1653]x[64,1653]^T
    {
        dim3 grid(1, (Tdim + 127) / 128, BE);
        sgemm2_nt<64, 4, 0><<<grid, blk>>>(S, Wt, O, Tdim, DE, Tdim,
                                           TT, (long long)TDE, (long long)TDE,
                                           nullptr, 0.f);
    }

    // 6) inverse reshape
    gather_x_kernel<<<(BT * Ddim + 255) / 256, blk>>>();

    // 7) final projection: out = X @ Wo^T + bo
    {
        dim3 grid(512 / 128, (BT + 127) / 128, 1);
        sgemm2_nt<128, 8, 1><<<grid, blk>>>(X, Wo, out, BT, Ddim, Ddim, 0, 0, 0, bo, 0.f);
    }
}